// round 10
// baseline (speedup 1.0000x reference)
#include <cuda_runtime.h>
#include <cuda_bf16.h>
#include <cstdint>
#include <math.h>

#define FULLMASK 0xFFFFFFFFu

// ===================== helpers (baseline compute_103 features only) =========
__device__ __forceinline__ uint32_t smem_u32(const void* p) {
    uint32_t a;
    asm("{ .reg .u64 t; cvta.to.shared.u64 t, %1; cvt.u32.u64 %0, t; }" : "=r"(a) : "l"(p));
    return a;
}
#define CP_ASYNC16(dst, src) \
    asm volatile("cp.async.cg.shared.global [%0], [%1], 16;" :: "r"((uint32_t)(dst)), "l"(src) : "memory")
#define CP_COMMIT() asm volatile("cp.async.commit_group;" ::: "memory")
#define CP_WAIT0()  asm volatile("cp.async.wait_group 0;" ::: "memory")
#define CP_WAIT1()  asm volatile("cp.async.wait_group 1;" ::: "memory")

#define LDSM_X4(r, a) \
    asm volatile("ldmatrix.sync.aligned.m8n8.x4.shared.b16 {%0,%1,%2,%3}, [%4];" \
        : "=r"((r)[0]), "=r"((r)[1]), "=r"((r)[2]), "=r"((r)[3]) : "r"(a))
#define MMA16816(d, a, b0, b1) \
    asm volatile("mma.sync.aligned.m16n8k16.row.col.f32.bf16.bf16.f32 " \
        "{%0,%1,%2,%3}, {%4,%5,%6,%7}, {%8,%9}, {%0,%1,%2,%3};" \
        : "+f"((d)[0]), "+f"((d)[1]), "+f"((d)[2]), "+f"((d)[3]) \
        : "r"((a)[0]), "r"((a)[1]), "r"((a)[2]), "r"((a)[3]), "r"(b0), "r"(b1))

__device__ __forceinline__ float ex2f(float y) {
    float z;
    asm("ex2.approx.f32 %0, %1;" : "=f"(z) : "f"(y));
    return z;
}
__device__ __forceinline__ float rcpf(float y) {
    float z;
    asm("rcp.approx.f32 %0, %1;" : "=f"(z) : "f"(y));
    return z;
}

// ===================== scratch ==============================================
__device__ float          d_f  [16 * 40 * 256];
__device__ float          d_e  [16 * 512 * 256];
__device__ __nv_bfloat16  d_Ah [16 * 512 * 1024];   // video split hi
__device__ __nv_bfloat16  d_Al [16 * 512 * 1024];   // video split lo
__device__ __nv_bfloat16  d_Gh [16 * 512 * 1024];   // tanh(cont) split hi
__device__ __nv_bfloat16  d_Gl [16 * 512 * 1024];
__device__ __nv_bfloat16  d_W1Th[256 * 1024];       // w1^T split (N-major)
__device__ __nv_bfloat16  d_W1Tl[256 * 1024];
__device__ __nv_bfloat16  d_W4Th[512 * 1024];       // w4^T padded 500->512, split
__device__ __nv_bfloat16  d_W4Tl[512 * 1024];

__device__ __forceinline__ void split_bf16(float v, __nv_bfloat16& h, __nv_bfloat16& l) {
    h = __float2bfloat16(v);
    l = __float2bfloat16(v - __bfloat162float(h));
}

// tanh via sigmoid: tanh(x) = 2/(1+2^(c*x)) - 1, c = -2*log2(e).
// Clamp exponent at 31 so 4-way batched reciprocals cannot overflow.
#define TANH_C (-2.8853900817779268f)

// Batched reciprocal of 4 positive values w[0..3] -> inv[0..3], 1 MUFU.RCP.
__device__ __forceinline__ void rcp4(const float* w, float* inv) {
    float s1 = w[0] * w[1];
    float s2 = w[2] * w[3];
    float r  = rcpf(s1 * s2);
    float t01 = r * s2;      // 1/(w0*w1)
    float t23 = r * s1;      // 1/(w2*w3)
    inv[0] = t01 * w[1];
    inv[1] = t01 * w[0];
    inv[2] = t23 * w[3];
    inv[3] = t23 * w[2];
}

// ===================== small prep kernels ===================================
__global__ void split_kernel(const float* __restrict__ src,
                             __nv_bfloat16* __restrict__ dh,
                             __nv_bfloat16* __restrict__ dl, int n4) {
    int i = blockIdx.x * 256 + threadIdx.x;
    if (i >= n4) return;
    float4 v = ((const float4*)src)[i];
    __nv_bfloat16 h[4], l[4];
    split_bf16(v.x, h[0], l[0]); split_bf16(v.y, h[1], l[1]);
    split_bf16(v.z, h[2], l[2]); split_bf16(v.w, h[3], l[3]);
    ((uint2*)dh)[i] = *(uint2*)h;
    ((uint2*)dl)[i] = *(uint2*)l;
}

// src [K, Nsrc] f32 -> dst [Ndst, K] bf16 (hi/lo), zero-padded rows >= Nsrc
__global__ void transpose_split_kernel(const float* __restrict__ src,
                                       __nv_bfloat16* __restrict__ dh,
                                       __nv_bfloat16* __restrict__ dl,
                                       int K, int Nsrc) {
    __shared__ float tile[32][33];
    int tx = threadIdx.x, ty = threadIdx.y;
    int bx = blockIdx.x, by = blockIdx.y;
    #pragma unroll
    for (int j = 0; j < 32; j += 8) {
        int k = by * 32 + ty + j;
        int n = bx * 32 + tx;
        tile[ty + j][tx] = (n < Nsrc) ? src[(size_t)k * Nsrc + n] : 0.0f;
    }
    __syncthreads();
    #pragma unroll
    for (int j = 0; j < 32; j += 8) {
        int n = bx * 32 + ty + j;
        int k = by * 32 + tx;
        float v = tile[tx][ty + j];
        __nv_bfloat16 h, l; split_bf16(v, h, l);
        dh[(size_t)n * K + k] = h;
        dl[(size_t)n * K + k] = l;
    }
}

// ===================== f = text @ w2 ========================================
__global__ void __launch_bounds__(256) text_proj_kernel(
        const float* __restrict__ text, const float* __restrict__ w2) {
    __shared__ float tr[304];
    int row = blockIdx.x;
    const float* trow = text + (size_t)row * 300;
    for (int k = threadIdx.x; k < 300; k += 256) tr[k] = trow[k];
    __syncthreads();
    int col = threadIdx.x;
    float a0 = 0.f, a1 = 0.f, a2 = 0.f, a3 = 0.f;
    #pragma unroll 1
    for (int k = 0; k < 300; k += 4) {
        a0 = fmaf(tr[k + 0], w2[(k + 0) * 256 + col], a0);
        a1 = fmaf(tr[k + 1], w2[(k + 1) * 256 + col], a1);
        a2 = fmaf(tr[k + 2], w2[(k + 2) * 256 + col], a2);
        a3 = fmaf(tr[k + 3], w2[(k + 3) * 256 + col], a3);
    }
    d_f[row * 256 + col] = (a0 + a1) + (a2 + a3);
}

// ===================== bf16x2 GEMM via mma.sync (HMMA) ======================
// C[M,N] = A@B, D += Ah*Bh + Ah*Bl + Al*Bh (fp32 accum).
// A: [M,K] bf16 row-major (hi/lo). B: TRANSPOSED [N,K] bf16 row-major (hi/lo).
// CTA tile 128x64, BK=32, 4 warps (warp tile 64x32), 2-stage cp.async.
// Small tile -> 30KB/stage -> 3 CTAs/SM (3 warps/SMSP) for latency hiding.
static constexpr int RS      = 80;            // smem row stride bytes
static constexpr int ATILE   = 128 * RS;      // 10240
static constexpr int BTILE   = 64 * RS;       // 5120
static constexpr int STAGE_B = 2 * ATILE + 2 * BTILE;  // 30720
static constexpr int SMEM_DYN_GEMM = 2 * STAGE_B;      // 61440

template <bool HAS_BIAS>
__global__ void __launch_bounds__(128, 3) mma_gemm_kernel(
        const __nv_bfloat16* __restrict__ Ah, const __nv_bfloat16* __restrict__ Al,
        const __nv_bfloat16* __restrict__ Bh, const __nv_bfloat16* __restrict__ Bl,
        float* __restrict__ C, const float* __restrict__ bias,
        int K, int Nreal, int ldc) {
    extern __shared__ __align__(128) char smem[];
    const uint32_t sb = smem_u32(smem);
    const int tid  = threadIdx.x;
    const int lane = tid & 31;
    const int wid  = tid >> 5;
    const int row0 = blockIdx.x * 128;
    const int col0 = blockIdx.y * 64;
    const int nc   = K >> 5;                 // BK=32

    // warp tiling: 2 (m) x 2 (n); warp tile 64x32
    const int m0 = (wid & 1) * 64;
    const int n0 = (wid >> 1) * 32;

    float acc[4][4][4];
    #pragma unroll
    for (int mi = 0; mi < 4; mi++)
        #pragma unroll
        for (int ni = 0; ni < 4; ni++)
            #pragma unroll
            for (int j = 0; j < 4; j++) acc[mi][ni][j] = 0.f;

    // ldmatrix lane address components
    const int q = lane >> 3;
    const uint32_t a_row = (uint32_t)((lane & 7) + (q & 1) * 8);
    const uint32_t a_kb  = (uint32_t)(q >> 1) * 16;
    const uint32_t b_row = (uint32_t)((lane & 7) + (q >> 1) * 8);
    const uint32_t b_kb  = (uint32_t)(q & 1) * 16;

    // ---- stage loader: 12 cp.async of 16B per thread (statically mapped) ----
    auto load_stage = [&](uint32_t s, int kt) {
        #pragma unroll
        for (int qq = 0; qq < 4; qq++) {                  // Ah: 512 chunks
            int u = tid + 128 * qq;
            int r = u >> 2, c = u & 3;
            uint32_t so = (uint32_t)(r * RS + c * 16);
            size_t ga = (size_t)(row0 + r) * K + kt + c * 8;
            CP_ASYNC16(s + so,         Ah + ga);
            CP_ASYNC16(s + ATILE + so, Al + ga);
        }
        #pragma unroll
        for (int qq = 0; qq < 2; qq++) {                  // B: 256 chunks each
            int u = tid + 128 * qq;
            int r = u >> 2, c = u & 3;
            uint32_t so = (uint32_t)(r * RS + c * 16);
            size_t gb = (size_t)(col0 + r) * K + kt + c * 8;
            CP_ASYNC16(s + 2 * ATILE + so,         Bh + gb);
            CP_ASYNC16(s + 2 * ATILE + BTILE + so, Bl + gb);
        }
        CP_COMMIT();
    };

    load_stage(sb, 0);

    #pragma unroll 1
    for (int i = 0; i < nc; i++) {
        if (i + 1 < nc) {
            load_stage(sb + ((i + 1) & 1) * STAGE_B, (i + 1) << 5);
            CP_WAIT1();
        } else {
            CP_WAIT0();
        }
        __syncthreads();
        const uint32_t s = sb + (i & 1) * STAGE_B;

        #pragma unroll
        for (int kk = 0; kk < 32; kk += 16) {
            uint32_t ah[4][4], al[4][4];
            #pragma unroll
            for (int mi = 0; mi < 4; mi++) {
                uint32_t aa = s + (uint32_t)(m0 + mi * 16 + a_row) * RS
                            + (uint32_t)kk * 2 + a_kb;
                LDSM_X4(ah[mi], aa);
                LDSM_X4(al[mi], aa + ATILE);
            }
            uint32_t bh0[4], bh1[4], bl0[4], bl1[4];
            #pragma unroll
            for (int nn = 0; nn < 2; nn++) {
                uint32_t ba = s + 2 * ATILE
                            + (uint32_t)(n0 + nn * 16 + b_row) * RS
                            + (uint32_t)kk * 2 + b_kb;
                uint32_t t[4];
                LDSM_X4(t, ba);
                bh0[2 * nn] = t[0]; bh1[2 * nn] = t[1];
                bh0[2 * nn + 1] = t[2]; bh1[2 * nn + 1] = t[3];
                LDSM_X4(t, ba + BTILE);
                bl0[2 * nn] = t[0]; bl1[2 * nn] = t[1];
                bl0[2 * nn + 1] = t[2]; bl1[2 * nn + 1] = t[3];
            }
            #pragma unroll
            for (int mi = 0; mi < 4; mi++)
                #pragma unroll
                for (int ni = 0; ni < 4; ni++)
                    MMA16816(acc[mi][ni], ah[mi], bh0[ni], bh1[ni]);
            #pragma unroll
            for (int mi = 0; mi < 4; mi++)
                #pragma unroll
                for (int ni = 0; ni < 4; ni++)
                    MMA16816(acc[mi][ni], ah[mi], bl0[ni], bl1[ni]);
            #pragma unroll
            for (int mi = 0; mi < 4; mi++)
                #pragma unroll
                for (int ni = 0; ni < 4; ni++)
                    MMA16816(acc[mi][ni], al[mi], bh0[ni], bh1[ni]);
        }
        __syncthreads();
    }

    // ---- epilogue: direct register -> global; bias read raw (unpadded) ----
    const int g  = lane >> 2;
    const int tg = lane & 3;
    #pragma unroll
    for (int mi = 0; mi < 4; mi++) {
        int row = row0 + m0 + mi * 16 + g;
        #pragma unroll
        for (int ni = 0; ni < 4; ni++) {
            int col = col0 + n0 + ni * 8 + tg * 2;
            if (col + 2 <= Nreal) {
                float bx = 0.f, by = 0.f;
                if (HAS_BIAS) { float2 bv = *(const float2*)(bias + col); bx = bv.x; by = bv.y; }
                float2 v0 = make_float2(acc[mi][ni][0] + bx, acc[mi][ni][1] + by);
                float2 v1 = make_float2(acc[mi][ni][2] + bx, acc[mi][ni][3] + by);
                *(float2*)&C[(size_t)row * ldc + col]       = v0;
                *(float2*)&C[(size_t)(row + 8) * ldc + col] = v1;
            }
        }
    }
}

// ===================== fused attention core =================================
// tanh via sigmoid + 4-way batched reciprocal: 1.25 MUFU per tanh.
__global__ void __launch_bounds__(256) attn_kernel(
        const float* __restrict__ w3, const float* __restrict__ bias) {
    __shared__ float fs[40 * 256];
    __shared__ float attns[8][40];
    __shared__ float w3s[256];

    const int tid  = threadIdx.x;
    const int lane = tid & 31;
    const int wid  = tid >> 5;
    const int row0 = blockIdx.x * 8;
    const int b    = row0 >> 9;

    const float* fsrc = d_f + (size_t)b * 40 * 256;
    for (int i = tid; i < 40 * 256 / 4; i += 256)
        ((float4*)fs)[i] = ((const float4*)fsrc)[i];
    w3s[tid] = w3[tid];
    __syncthreads();

    const int row = row0 + wid;
    float e_k[8], ebc_k[8], w32_k[8];
    #pragma unroll
    for (int k = 0; k < 8; k++) {
        int a    = lane + 32 * k;
        e_k[k]   = d_e[(size_t)row * 256 + a];
        ebc_k[k] = (e_k[k] + bias[a]) * TANH_C;
        w32_k[k] = 2.0f * w3s[a];
    }

    // logits
    float l0 = 0.f, l1 = -INFINITY;
    #pragma unroll 1
    for (int t = 0; t < 40; t++) {
        const float* fr = fs + t * 256;
        float w[8];
        #pragma unroll
        for (int k = 0; k < 8; k++) {
            float y = fmaf(fr[lane + 32 * k], TANH_C, ebc_k[k]);
            y = fminf(y, 31.0f);
            w[k] = ex2f(y) + 1.0f;
        }
        float inv[8];
        rcp4(w, inv);
        rcp4(w + 4, inv + 4);
        float acc = 0.f;
        #pragma unroll
        for (int k = 0; k < 8; k++) acc = fmaf(w32_k[k], inv[k], acc);
        #pragma unroll
        for (int off = 16; off; off >>= 1)
            acc += __shfl_xor_sync(FULLMASK, acc, off);
        if (t < 32) { if (lane == t)      l0 = acc; }
        else        { if (lane == t - 32) l1 = acc; }
    }

    // softmax over 40 logits
    float m = fmaxf(l0, l1);
    #pragma unroll
    for (int off = 16; off; off >>= 1)
        m = fmaxf(m, __shfl_xor_sync(FULLMASK, m, off));
    float p0 = __expf(l0 - m);
    float p1 = (lane < 8) ? __expf(l1 - m) : 0.0f;
    float s  = p0 + p1;
    #pragma unroll
    for (int off = 16; off; off >>= 1)
        s += __shfl_xor_sync(FULLMASK, s, off);
    float invs = __fdividef(1.0f, s);
    attns[wid][lane] = p0 * invs;
    if (lane < 8) attns[wid][32 + lane] = p1 * invs;
    __syncwarp();

    // text_attn
    float ta[8] = {0, 0, 0, 0, 0, 0, 0, 0};
    #pragma unroll 1
    for (int t = 0; t < 40; t++) {
        float wgt = attns[wid][t];
        const float* fr = fs + t * 256;
        #pragma unroll
        for (int k = 0; k < 8; k++)
            ta[k] = fmaf(wgt, fr[lane + 32 * k], ta[k]);
    }

    // g = tanh(concat[e, ta, e*ta, e-ta]) -> bf16 hi/lo split
    size_t gbase = (size_t)row * 1024;
    #pragma unroll
    for (int k = 0; k < 8; k++) {
        int a = lane + 32 * k;
        float ev = e_k[k], tv = ta[k];
        float x[4] = {ev, tv, ev * tv, ev - tv};
        float w[4], inv[4];
        #pragma unroll
        for (int j = 0; j < 4; j++) {
            float y = fminf(x[j] * TANH_C, 31.0f);
            w[j] = ex2f(y) + 1.0f;
        }
        rcp4(w, inv);
        #pragma unroll
        for (int j = 0; j < 4; j++) {
            float tval = fmaf(2.0f, inv[j], -1.0f);
            __nv_bfloat16 h, l;
            split_bf16(tval, h, l);
            d_Gh[gbase + j * 256 + a] = h;
            d_Gl[gbase + j * 256 + a] = l;
        }
    }
}

// ===================== launch ===============================================
extern "C" void kernel_launch(void* const* d_in, const int* in_sizes, int n_in,
                              void* d_out, int out_size) {
    const float* video = (const float*)d_in[0];
    const float* text  = (const float*)d_in[1];
    const float* w1    = (const float*)d_in[2];
    const float* w2    = (const float*)d_in[3];
    const float* w3    = (const float*)d_in[4];
    const float* bias  = (const float*)d_in[5];
    const float* w4    = (const float*)d_in[6];
    const float* b4    = (const float*)d_in[7];
    float* out = (float*)d_out;

    float *e_p;
    __nv_bfloat16 *Ah_p, *Al_p, *Gh_p, *Gl_p, *W1Th_p, *W1Tl_p, *W4Th_p, *W4Tl_p;
    cudaGetSymbolAddress((void**)&e_p,    d_e);
    cudaGetSymbolAddress((void**)&Ah_p,   d_Ah);
    cudaGetSymbolAddress((void**)&Al_p,   d_Al);
    cudaGetSymbolAddress((void**)&Gh_p,   d_Gh);
    cudaGetSymbolAddress((void**)&Gl_p,   d_Gl);
    cudaGetSymbolAddress((void**)&W1Th_p, d_W1Th);
    cudaGetSymbolAddress((void**)&W1Tl_p, d_W1Tl);
    cudaGetSymbolAddress((void**)&W4Th_p, d_W4Th);
    cudaGetSymbolAddress((void**)&W4Tl_p, d_W4Tl);

    cudaFuncSetAttribute(mma_gemm_kernel<false>,
                         cudaFuncAttributeMaxDynamicSharedMemorySize, SMEM_DYN_GEMM);
    cudaFuncSetAttribute(mma_gemm_kernel<true>,
                         cudaFuncAttributeMaxDynamicSharedMemorySize, SMEM_DYN_GEMM);

    // prep
    split_kernel<<<(16 * 512 * 1024 / 4 + 255) / 256, 256>>>(video, Ah_p, Al_p,
                                                             16 * 512 * 1024 / 4);
    transpose_split_kernel<<<dim3(256 / 32, 1024 / 32), dim3(32, 8)>>>(
        w1, W1Th_p, W1Tl_p, 1024, 256);
    transpose_split_kernel<<<dim3(512 / 32, 1024 / 32), dim3(32, 8)>>>(
        w4, W4Th_p, W4Tl_p, 1024, 500);
    text_proj_kernel<<<640, 256>>>(text, w2);

    // e = video @ w1 : M=8192, N=256, K=1024
    mma_gemm_kernel<false><<<dim3(64, 4), 128, SMEM_DYN_GEMM>>>(
        Ah_p, Al_p, W1Th_p, W1Tl_p, e_p, nullptr, 1024, 256, 256);

    attn_kernel<<<1024, 256>>>(w3, bias);

    // out = g @ w4 + b4 : M=8192, N=512(pad of 500), K=1024
    mma_gemm_kernel<true><<<dim3(64, 8), 128, SMEM_DYN_GEMM>>>(
        Gh_p, Gl_p, W4Th_p, W4Tl_p, out, b4, 1024, 500, 500);
}

// round 11
// speedup vs baseline: 1.0325x; 1.0325x over previous
#include <cuda_runtime.h>
#include <cuda_bf16.h>
#include <cstdint>
#include <math.h>

#define FULLMASK 0xFFFFFFFFu

// ===================== helpers (baseline compute_103 features only) =========
__device__ __forceinline__ uint32_t smem_u32(const void* p) {
    uint32_t a;
    asm("{ .reg .u64 t; cvta.to.shared.u64 t, %1; cvt.u32.u64 %0, t; }" : "=r"(a) : "l"(p));
    return a;
}
#define CP_ASYNC16(dst, src) \
    asm volatile("cp.async.cg.shared.global [%0], [%1], 16;" :: "r"((uint32_t)(dst)), "l"(src) : "memory")
#define CP_COMMIT() asm volatile("cp.async.commit_group;" ::: "memory")
#define CP_WAIT0()  asm volatile("cp.async.wait_group 0;" ::: "memory")
#define CP_WAIT1()  asm volatile("cp.async.wait_group 1;" ::: "memory")

#define LDSM_X4(r, a) \
    asm volatile("ldmatrix.sync.aligned.m8n8.x4.shared.b16 {%0,%1,%2,%3}, [%4];" \
        : "=r"((r)[0]), "=r"((r)[1]), "=r"((r)[2]), "=r"((r)[3]) : "r"(a))
#define MMA16816(d, a, b0, b1) \
    asm volatile("mma.sync.aligned.m16n8k16.row.col.f32.bf16.bf16.f32 " \
        "{%0,%1,%2,%3}, {%4,%5,%6,%7}, {%8,%9}, {%0,%1,%2,%3};" \
        : "+f"((d)[0]), "+f"((d)[1]), "+f"((d)[2]), "+f"((d)[3]) \
        : "r"((a)[0]), "r"((a)[1]), "r"((a)[2]), "r"((a)[3]), "r"(b0), "r"(b1))

__device__ __forceinline__ float ex2f(float y) {
    float z;
    asm("ex2.approx.f32 %0, %1;" : "=f"(z) : "f"(y));
    return z;
}
__device__ __forceinline__ float rcpf(float y) {
    float z;
    asm("rcp.approx.f32 %0, %1;" : "=f"(z) : "f"(y));
    return z;
}

// ===================== scratch ==============================================
__device__ float          d_f  [16 * 40 * 256];
__device__ float          d_e  [16 * 512 * 256];
__device__ __nv_bfloat16  d_Ah [16 * 512 * 1024];   // video split hi
__device__ __nv_bfloat16  d_Al [16 * 512 * 1024];   // video split lo
__device__ __nv_bfloat16  d_Gh [16 * 512 * 1024];   // tanh(cont) split hi
__device__ __nv_bfloat16  d_Gl [16 * 512 * 1024];
__device__ __nv_bfloat16  d_W1Th[256 * 1024];       // w1^T split (N-major)
__device__ __nv_bfloat16  d_W1Tl[256 * 1024];
__device__ __nv_bfloat16  d_W4Th[512 * 1024];       // w4^T padded 500->512, split
__device__ __nv_bfloat16  d_W4Tl[512 * 1024];

__device__ __forceinline__ void split_bf16(float v, __nv_bfloat16& h, __nv_bfloat16& l) {
    h = __float2bfloat16(v);
    l = __float2bfloat16(v - __bfloat162float(h));
}

// tanh via sigmoid: tanh(x) = 2/(1+2^(c*x)) - 1, c = -2*log2(e).
// Clamp exponent at 31 so 4-way batched reciprocals cannot overflow.
#define TANH_C (-2.8853900817779268f)

// Batched reciprocal of 4 positive values w[0..3] -> inv[0..3], 1 MUFU.RCP.
__device__ __forceinline__ void rcp4(const float* w, float* inv) {
    float s1 = w[0] * w[1];
    float s2 = w[2] * w[3];
    float r  = rcpf(s1 * s2);
    float t01 = r * s2;      // 1/(w0*w1)
    float t23 = r * s1;      // 1/(w2*w3)
    inv[0] = t01 * w[1];
    inv[1] = t01 * w[0];
    inv[2] = t23 * w[3];
    inv[3] = t23 * w[2];
}

// ===================== small prep kernels ===================================
__global__ void split_kernel(const float* __restrict__ src,
                             __nv_bfloat16* __restrict__ dh,
                             __nv_bfloat16* __restrict__ dl, int n4) {
    int i = blockIdx.x * 256 + threadIdx.x;
    if (i >= n4) return;
    float4 v = ((const float4*)src)[i];
    __nv_bfloat16 h[4], l[4];
    split_bf16(v.x, h[0], l[0]); split_bf16(v.y, h[1], l[1]);
    split_bf16(v.z, h[2], l[2]); split_bf16(v.w, h[3], l[3]);
    ((uint2*)dh)[i] = *(uint2*)h;
    ((uint2*)dl)[i] = *(uint2*)l;
}

// src [K, Nsrc] f32 -> dst [Ndst, K] bf16 (hi/lo), zero-padded rows >= Nsrc
__global__ void transpose_split_kernel(const float* __restrict__ src,
                                       __nv_bfloat16* __restrict__ dh,
                                       __nv_bfloat16* __restrict__ dl,
                                       int K, int Nsrc) {
    __shared__ float tile[32][33];
    int tx = threadIdx.x, ty = threadIdx.y;
    int bx = blockIdx.x, by = blockIdx.y;
    #pragma unroll
    for (int j = 0; j < 32; j += 8) {
        int k = by * 32 + ty + j;
        int n = bx * 32 + tx;
        tile[ty + j][tx] = (n < Nsrc) ? src[(size_t)k * Nsrc + n] : 0.0f;
    }
    __syncthreads();
    #pragma unroll
    for (int j = 0; j < 32; j += 8) {
        int n = bx * 32 + ty + j;
        int k = by * 32 + tx;
        float v = tile[tx][ty + j];
        __nv_bfloat16 h, l; split_bf16(v, h, l);
        dh[(size_t)n * K + k] = h;
        dl[(size_t)n * K + k] = l;
    }
}

// ===================== f = text @ w2  (row-blocked) =========================
// 8 rows per block (80 blocks). Each w2 element loaded once per block and
// reused across 8 rows -> 8 independent FMA chains per load; per-k order of
// accumulation matches the previous kernel (bit-identical f).
__global__ void __launch_bounds__(256) text_proj_kernel(
        const float* __restrict__ text, const float* __restrict__ w2) {
    __shared__ float ts[8][300];
    const int tid  = threadIdx.x;
    const int row0 = blockIdx.x * 8;                    // 0..632
    for (int i = tid; i < 8 * 300; i += 256) {
        int r = i / 300, k = i % 300;
        ts[r][k] = text[(size_t)(row0 + r) * 300 + k];
    }
    __syncthreads();
    const int col = tid;                                // 0..255
    float acc[8] = {0, 0, 0, 0, 0, 0, 0, 0};
    #pragma unroll 4
    for (int k = 0; k < 300; k++) {
        float wv = w2[k * 256 + col];
        #pragma unroll
        for (int r = 0; r < 8; r++)
            acc[r] = fmaf(ts[r][k], wv, acc[r]);
    }
    #pragma unroll
    for (int r = 0; r < 8; r++)
        d_f[(size_t)(row0 + r) * 256 + col] = acc[r];
}

// ===================== bf16x2 GEMM via mma.sync (HMMA) ======================
// C[M,N] = A@B, D += Ah*Bh + Ah*Bl + Al*Bh (fp32 accum).  [R9 config]
// A: [M,K] bf16 row-major (hi/lo). B: TRANSPOSED [N,K] bf16 row-major (hi/lo).
// CTA tile 128x128, BK=32, 4 warps (warp tile 64x64), 2-stage cp.async.
static constexpr int RS      = 80;           // smem row stride bytes
static constexpr int TILE_B  = 128 * RS;     // 10240
static constexpr int STAGE_B = 4 * TILE_B;   // 40960: Ah, Al, Bh, Bl
static constexpr int SMEM_DYN_GEMM = 2 * STAGE_B;  // 81920

template <bool HAS_BIAS>
__global__ void __launch_bounds__(128, 2) mma_gemm_kernel(
        const __nv_bfloat16* __restrict__ Ah, const __nv_bfloat16* __restrict__ Al,
        const __nv_bfloat16* __restrict__ Bh, const __nv_bfloat16* __restrict__ Bl,
        float* __restrict__ C, const float* __restrict__ bias,
        int K, int Nreal, int ldc) {
    extern __shared__ __align__(128) char smem[];
    const uint32_t sb = smem_u32(smem);
    const int tid  = threadIdx.x;
    const int lane = tid & 31;
    const int wid  = tid >> 5;
    const int row0 = blockIdx.x * 128;
    const int col0 = blockIdx.y * 128;
    const int nc   = K >> 5;                 // BK=32

    // warp tiling: 2 (m) x 2 (n)
    const int m0 = (wid & 1) * 64;
    const int n0 = (wid >> 1) * 64;

    float acc[4][8][4];
    #pragma unroll
    for (int mi = 0; mi < 4; mi++)
        #pragma unroll
        for (int ni = 0; ni < 8; ni++)
            #pragma unroll
            for (int j = 0; j < 4; j++) acc[mi][ni][j] = 0.f;

    // ldmatrix lane address components
    const int q = lane >> 3;
    const uint32_t a_row = (uint32_t)((lane & 7) + (q & 1) * 8);
    const uint32_t a_kb  = (uint32_t)(q >> 1) * 16;
    const uint32_t b_row = (uint32_t)((lane & 7) + (q >> 1) * 8);
    const uint32_t b_kb  = (uint32_t)(q & 1) * 16;

    // ---- stage loader: 16 cp.async of 16B per thread ----
    auto load_stage = [&](uint32_t s, int kt) {
        #pragma unroll
        for (int qq = 0; qq < 4; qq++) {
            int u = tid + 128 * qq;
            int r = u >> 2, cc = u & 3;
            uint32_t so = (uint32_t)(r * RS + cc * 16);
            size_t ga = (size_t)(row0 + r) * K + kt + cc * 8;
            size_t gb = (size_t)(col0 + r) * K + kt + cc * 8;
            CP_ASYNC16(s + so,              Ah + ga);
            CP_ASYNC16(s + TILE_B + so,     Al + ga);
            CP_ASYNC16(s + 2 * TILE_B + so, Bh + gb);
            CP_ASYNC16(s + 3 * TILE_B + so, Bl + gb);
        }
        CP_COMMIT();
    };

    load_stage(sb, 0);

    #pragma unroll 1
    for (int i = 0; i < nc; i++) {
        if (i + 1 < nc) {
            load_stage(sb + ((i + 1) & 1) * STAGE_B, (i + 1) << 5);
            CP_WAIT1();
        } else {
            CP_WAIT0();
        }
        __syncthreads();
        const uint32_t s = sb + (i & 1) * STAGE_B;

        #pragma unroll
        for (int kk = 0; kk < 32; kk += 16) {
            uint32_t ah[4][4], al[4][4];
            #pragma unroll
            for (int mi = 0; mi < 4; mi++) {
                uint32_t aa = s + (uint32_t)(m0 + mi * 16 + a_row) * RS
                            + (uint32_t)kk * 2 + a_kb;
                LDSM_X4(ah[mi], aa);
                LDSM_X4(al[mi], aa + TILE_B);
            }
            uint32_t bh0[8], bh1[8], bl0[8], bl1[8];
            #pragma unroll
            for (int nn = 0; nn < 4; nn++) {
                uint32_t ba = s + 2 * TILE_B
                            + (uint32_t)(n0 + nn * 16 + b_row) * RS
                            + (uint32_t)kk * 2 + b_kb;
                uint32_t t[4];
                LDSM_X4(t, ba);
                bh0[2 * nn] = t[0]; bh1[2 * nn] = t[1];
                bh0[2 * nn + 1] = t[2]; bh1[2 * nn + 1] = t[3];
                LDSM_X4(t, ba + TILE_B);
                bl0[2 * nn] = t[0]; bl1[2 * nn] = t[1];
                bl0[2 * nn + 1] = t[2]; bl1[2 * nn + 1] = t[3];
            }
            #pragma unroll
            for (int mi = 0; mi < 4; mi++)
                #pragma unroll
                for (int ni = 0; ni < 8; ni++)
                    MMA16816(acc[mi][ni], ah[mi], bh0[ni], bh1[ni]);
            #pragma unroll
            for (int mi = 0; mi < 4; mi++)
                #pragma unroll
                for (int ni = 0; ni < 8; ni++)
                    MMA16816(acc[mi][ni], ah[mi], bl0[ni], bl1[ni]);
            #pragma unroll
            for (int mi = 0; mi < 4; mi++)
                #pragma unroll
                for (int ni = 0; ni < 8; ni++)
                    MMA16816(acc[mi][ni], al[mi], bh0[ni], bh1[ni]);
        }
        __syncthreads();
    }

    // ---- epilogue: direct register -> global; bias read raw (unpadded) ----
    const int g  = lane >> 2;
    const int tg = lane & 3;
    #pragma unroll
    for (int mi = 0; mi < 4; mi++) {
        int row = row0 + m0 + mi * 16 + g;
        #pragma unroll
        for (int ni = 0; ni < 8; ni++) {
            int col = col0 + n0 + ni * 8 + tg * 2;
            if (col + 2 <= Nreal) {
                float bx = 0.f, by = 0.f;
                if (HAS_BIAS) { float2 bv = *(const float2*)(bias + col); bx = bv.x; by = bv.y; }
                float2 v0 = make_float2(acc[mi][ni][0] + bx, acc[mi][ni][1] + by);
                float2 v1 = make_float2(acc[mi][ni][2] + bx, acc[mi][ni][3] + by);
                *(float2*)&C[(size_t)row * ldc + col]       = v0;
                *(float2*)&C[(size_t)(row + 8) * ldc + col] = v1;
            }
        }
    }
}

// ===================== fused attention core =================================
// tanh via sigmoid + 4-way batched reciprocal: 1.25 MUFU per tanh.
__global__ void __launch_bounds__(256) attn_kernel(
        const float* __restrict__ w3, const float* __restrict__ bias) {
    __shared__ float fs[40 * 256];
    __shared__ float attns[8][40];
    __shared__ float w3s[256];

    const int tid  = threadIdx.x;
    const int lane = tid & 31;
    const int wid  = tid >> 5;
    const int row0 = blockIdx.x * 8;
    const int b    = row0 >> 9;

    const float* fsrc = d_f + (size_t)b * 40 * 256;
    for (int i = tid; i < 40 * 256 / 4; i += 256)
        ((float4*)fs)[i] = ((const float4*)fsrc)[i];
    w3s[tid] = w3[tid];
    __syncthreads();

    const int row = row0 + wid;
    float e_k[8], ebc_k[8], w32_k[8];
    #pragma unroll
    for (int k = 0; k < 8; k++) {
        int a    = lane + 32 * k;
        e_k[k]   = d_e[(size_t)row * 256 + a];
        ebc_k[k] = (e_k[k] + bias[a]) * TANH_C;
        w32_k[k] = 2.0f * w3s[a];
    }

    // logits
    float l0 = 0.f, l1 = -INFINITY;
    #pragma unroll 1
    for (int t = 0; t < 40; t++) {
        const float* fr = fs + t * 256;
        float w[8];
        #pragma unroll
        for (int k = 0; k < 8; k++) {
            float y = fmaf(fr[lane + 32 * k], TANH_C, ebc_k[k]);
            y = fminf(y, 31.0f);
            w[k] = ex2f(y) + 1.0f;
        }
        float inv[8];
        rcp4(w, inv);
        rcp4(w + 4, inv + 4);
        float acc = 0.f;
        #pragma unroll
        for (int k = 0; k < 8; k++) acc = fmaf(w32_k[k], inv[k], acc);
        #pragma unroll
        for (int off = 16; off; off >>= 1)
            acc += __shfl_xor_sync(FULLMASK, acc, off);
        if (t < 32) { if (lane == t)      l0 = acc; }
        else        { if (lane == t - 32) l1 = acc; }
    }

    // softmax over 40 logits
    float m = fmaxf(l0, l1);
    #pragma unroll
    for (int off = 16; off; off >>= 1)
        m = fmaxf(m, __shfl_xor_sync(FULLMASK, m, off));
    float p0 = __expf(l0 - m);
    float p1 = (lane < 8) ? __expf(l1 - m) : 0.0f;
    float s  = p0 + p1;
    #pragma unroll
    for (int off = 16; off; off >>= 1)
        s += __shfl_xor_sync(FULLMASK, s, off);
    float invs = __fdividef(1.0f, s);
    attns[wid][lane] = p0 * invs;
    if (lane < 8) attns[wid][32 + lane] = p1 * invs;
    __syncwarp();

    // text_attn
    float ta[8] = {0, 0, 0, 0, 0, 0, 0, 0};
    #pragma unroll 1
    for (int t = 0; t < 40; t++) {
        float wgt = attns[wid][t];
        const float* fr = fs + t * 256;
        #pragma unroll
        for (int k = 0; k < 8; k++)
            ta[k] = fmaf(wgt, fr[lane + 32 * k], ta[k]);
    }

    // g = tanh(concat[e, ta, e*ta, e-ta]) -> bf16 hi/lo split
    size_t gbase = (size_t)row * 1024;
    #pragma unroll
    for (int k = 0; k < 8; k++) {
        int a = lane + 32 * k;
        float ev = e_k[k], tv = ta[k];
        float x[4] = {ev, tv, ev * tv, ev - tv};
        float w[4], inv[4];
        #pragma unroll
        for (int j = 0; j < 4; j++) {
            float y = fminf(x[j] * TANH_C, 31.0f);
            w[j] = ex2f(y) + 1.0f;
        }
        rcp4(w, inv);
        #pragma unroll
        for (int j = 0; j < 4; j++) {
            float tval = fmaf(2.0f, inv[j], -1.0f);
            __nv_bfloat16 h, l;
            split_bf16(tval, h, l);
            d_Gh[gbase + j * 256 + a] = h;
            d_Gl[gbase + j * 256 + a] = l;
        }
    }
}

// ===================== launch ===============================================
extern "C" void kernel_launch(void* const* d_in, const int* in_sizes, int n_in,
                              void* d_out, int out_size) {
    const float* video = (const float*)d_in[0];
    const float* text  = (const float*)d_in[1];
    const float* w1    = (const float*)d_in[2];
    const float* w2    = (const float*)d_in[3];
    const float* w3    = (const float*)d_in[4];
    const float* bias  = (const float*)d_in[5];
    const float* w4    = (const float*)d_in[6];
    const float* b4    = (const float*)d_in[7];
    float* out = (float*)d_out;

    float *e_p;
    __nv_bfloat16 *Ah_p, *Al_p, *Gh_p, *Gl_p, *W1Th_p, *W1Tl_p, *W4Th_p, *W4Tl_p;
    cudaGetSymbolAddress((void**)&e_p,    d_e);
    cudaGetSymbolAddress((void**)&Ah_p,   d_Ah);
    cudaGetSymbolAddress((void**)&Al_p,   d_Al);
    cudaGetSymbolAddress((void**)&Gh_p,   d_Gh);
    cudaGetSymbolAddress((void**)&Gl_p,   d_Gl);
    cudaGetSymbolAddress((void**)&W1Th_p, d_W1Th);
    cudaGetSymbolAddress((void**)&W1Tl_p, d_W1Tl);
    cudaGetSymbolAddress((void**)&W4Th_p, d_W4Th);
    cudaGetSymbolAddress((void**)&W4Tl_p, d_W4Tl);

    cudaFuncSetAttribute(mma_gemm_kernel<false>,
                         cudaFuncAttributeMaxDynamicSharedMemorySize, SMEM_DYN_GEMM);
    cudaFuncSetAttribute(mma_gemm_kernel<true>,
                         cudaFuncAttributeMaxDynamicSharedMemorySize, SMEM_DYN_GEMM);

    // prep
    split_kernel<<<(16 * 512 * 1024 / 4 + 255) / 256, 256>>>(video, Ah_p, Al_p,
                                                             16 * 512 * 1024 / 4);
    transpose_split_kernel<<<dim3(256 / 32, 1024 / 32), dim3(32, 8)>>>(
        w1, W1Th_p, W1Tl_p, 1024, 256);
    transpose_split_kernel<<<dim3(512 / 32, 1024 / 32), dim3(32, 8)>>>(
        w4, W4Th_p, W4Tl_p, 1024, 500);
    text_proj_kernel<<<80, 256>>>(text, w2);

    // e = video @ w1 : M=8192, N=256, K=1024
    mma_gemm_kernel<false><<<dim3(64, 2), 128, SMEM_DYN_GEMM>>>(
        Ah_p, Al_p, W1Th_p, W1Tl_p, e_p, nullptr, 1024, 256, 256);

    attn_kernel<<<1024, 256>>>(w3, bias);

    // out = g @ w4 + b4 : M=8192, N=512(pad of 500), K=1024
    mma_gemm_kernel<true><<<dim3(64, 4), 128, SMEM_DYN_GEMM>>>(
        Gh_p, Gl_p, W4Th_p, W4Tl_p, out, b4, 1024, 500, 500);
}

// round 12
// speedup vs baseline: 1.1095x; 1.0746x over previous
#include <cuda_runtime.h>
#include <cuda_bf16.h>
#include <cstdint>
#include <math.h>

#define FULLMASK 0xFFFFFFFFu

// ===================== helpers (baseline compute_103 features only) =========
__device__ __forceinline__ uint32_t smem_u32(const void* p) {
    uint32_t a;
    asm("{ .reg .u64 t; cvta.to.shared.u64 t, %1; cvt.u32.u64 %0, t; }" : "=r"(a) : "l"(p));
    return a;
}
#define CP_ASYNC16(dst, src) \
    asm volatile("cp.async.cg.shared.global [%0], [%1], 16;" :: "r"((uint32_t)(dst)), "l"(src) : "memory")
#define CP_COMMIT() asm volatile("cp.async.commit_group;" ::: "memory")
#define CP_WAIT0()  asm volatile("cp.async.wait_group 0;" ::: "memory")
#define CP_WAIT1()  asm volatile("cp.async.wait_group 1;" ::: "memory")

#define LDSM_X4(r, a) \
    asm volatile("ldmatrix.sync.aligned.m8n8.x4.shared.b16 {%0,%1,%2,%3}, [%4];" \
        : "=r"((r)[0]), "=r"((r)[1]), "=r"((r)[2]), "=r"((r)[3]) : "r"(a))
#define MMA16816(d, a, b0, b1) \
    asm volatile("mma.sync.aligned.m16n8k16.row.col.f32.bf16.bf16.f32 " \
        "{%0,%1,%2,%3}, {%4,%5,%6,%7}, {%8,%9}, {%0,%1,%2,%3};" \
        : "+f"((d)[0]), "+f"((d)[1]), "+f"((d)[2]), "+f"((d)[3]) \
        : "r"((a)[0]), "r"((a)[1]), "r"((a)[2]), "r"((a)[3]), "r"(b0), "r"(b1))

__device__ __forceinline__ float ex2f(float y) {
    float z;
    asm("ex2.approx.f32 %0, %1;" : "=f"(z) : "f"(y));
    return z;
}
__device__ __forceinline__ float rcpf(float y) {
    float z;
    asm("rcp.approx.f32 %0, %1;" : "=f"(z) : "f"(y));
    return z;
}

// ===================== scratch ==============================================
__device__ float          d_f  [16 * 40 * 256];
__device__ float          d_fp [4][16 * 40 * 256];  // split-K partials for f
__device__ float          d_e  [16 * 512 * 256];
__device__ __nv_bfloat16  d_Ah [16 * 512 * 1024];   // video split hi
__device__ __nv_bfloat16  d_Al [16 * 512 * 1024];   // video split lo
__device__ __nv_bfloat16  d_Gh [16 * 512 * 1024];   // tanh(cont) split hi
__device__ __nv_bfloat16  d_Gl [16 * 512 * 1024];
__device__ __nv_bfloat16  d_W1Th[256 * 1024];       // w1^T split (N-major)
__device__ __nv_bfloat16  d_W1Tl[256 * 1024];
__device__ __nv_bfloat16  d_W4Th[512 * 1024];       // w4^T padded 500->512, split
__device__ __nv_bfloat16  d_W4Tl[512 * 1024];

__device__ __forceinline__ void split_bf16(float v, __nv_bfloat16& h, __nv_bfloat16& l) {
    h = __float2bfloat16(v);
    l = __float2bfloat16(v - __bfloat162float(h));
}

// tanh via sigmoid: tanh(x) = 2/(1+2^(c*x)) - 1, c = -2*log2(e).
// Clamp exponent at 31 so 4-way batched reciprocals cannot overflow.
#define TANH_C (-2.8853900817779268f)

// Batched reciprocal of 4 positive values w[0..3] -> inv[0..3], 1 MUFU.RCP.
__device__ __forceinline__ void rcp4(const float* w, float* inv) {
    float s1 = w[0] * w[1];
    float s2 = w[2] * w[3];
    float r  = rcpf(s1 * s2);
    float t01 = r * s2;      // 1/(w0*w1)
    float t23 = r * s1;      // 1/(w2*w3)
    inv[0] = t01 * w[1];
    inv[1] = t01 * w[0];
    inv[2] = t23 * w[3];
    inv[3] = t23 * w[2];
}

// ===================== small prep kernels ===================================
__global__ void split_kernel(const float* __restrict__ src,
                             __nv_bfloat16* __restrict__ dh,
                             __nv_bfloat16* __restrict__ dl, int n4) {
    int i = blockIdx.x * 256 + threadIdx.x;
    if (i >= n4) return;
    float4 v = ((const float4*)src)[i];
    __nv_bfloat16 h[4], l[4];
    split_bf16(v.x, h[0], l[0]); split_bf16(v.y, h[1], l[1]);
    split_bf16(v.z, h[2], l[2]); split_bf16(v.w, h[3], l[3]);
    ((uint2*)dh)[i] = *(uint2*)h;
    ((uint2*)dl)[i] = *(uint2*)l;
}

// src [K, Nsrc] f32 -> dst [Ndst, K] bf16 (hi/lo), zero-padded rows >= Nsrc
__global__ void transpose_split_kernel(const float* __restrict__ src,
                                       __nv_bfloat16* __restrict__ dh,
                                       __nv_bfloat16* __restrict__ dl,
                                       int K, int Nsrc) {
    __shared__ float tile[32][33];
    int tx = threadIdx.x, ty = threadIdx.y;
    int bx = blockIdx.x, by = blockIdx.y;
    #pragma unroll
    for (int j = 0; j < 32; j += 8) {
        int k = by * 32 + ty + j;
        int n = bx * 32 + tx;
        tile[ty + j][tx] = (n < Nsrc) ? src[(size_t)k * Nsrc + n] : 0.0f;
    }
    __syncthreads();
    #pragma unroll
    for (int j = 0; j < 32; j += 8) {
        int n = bx * 32 + ty + j;
        int k = by * 32 + tx;
        float v = tile[tx][ty + j];
        __nv_bfloat16 h, l; split_bf16(v, h, l);
        dh[(size_t)n * K + k] = h;
        dl[(size_t)n * K + k] = l;
    }
}

// ===================== f = text @ w2  (split-K, row-blocked) ================
// grid (80, 4): 8 rows x 75-k-chunk per block -> 320 blocks (full chip),
// w2 element loaded once per 8 rows, partials reduced deterministically.
__global__ void __launch_bounds__(256) text_proj_partial_kernel(
        const float* __restrict__ text, const float* __restrict__ w2) {
    __shared__ float ts[8][76];
    const int tid  = threadIdx.x;
    const int row0 = blockIdx.x * 8;                   // 0..632
    const int kc   = blockIdx.y;                       // 0..3
    const int k0   = kc * 75;
    for (int i = tid; i < 8 * 75; i += 256) {
        int r = i / 75, k = i % 75;
        ts[r][k] = text[(size_t)(row0 + r) * 300 + k0 + k];
    }
    __syncthreads();
    const int col = tid;                               // 0..255
    float acc[8] = {0, 0, 0, 0, 0, 0, 0, 0};
    #pragma unroll 5
    for (int k = 0; k < 75; k++) {
        float wv = w2[(k0 + k) * 256 + col];
        #pragma unroll
        for (int r = 0; r < 8; r++)
            acc[r] = fmaf(ts[r][k], wv, acc[r]);
    }
    #pragma unroll
    for (int r = 0; r < 8; r++)
        d_fp[kc][(size_t)(row0 + r) * 256 + col] = acc[r];
}

__global__ void __launch_bounds__(256) text_proj_reduce_kernel() {
    int i = blockIdx.x * 256 + threadIdx.x;            // 0..163839
    float s = (d_fp[0][i] + d_fp[1][i]) + (d_fp[2][i] + d_fp[3][i]);
    d_f[i] = s;
}

// ===================== bf16x2 GEMM via mma.sync (HMMA) ======================
// C[M,N] = A@B, D += Ah*Bh + Ah*Bl + Al*Bh (fp32 accum).  [R9 config]
// A: [M,K] bf16 row-major (hi/lo). B: TRANSPOSED [N,K] bf16 row-major (hi/lo).
// CTA tile 128x128, BK=32, 4 warps (warp tile 64x64), 2-stage cp.async.
static constexpr int RS      = 80;           // smem row stride bytes
static constexpr int TILE_B  = 128 * RS;     // 10240
static constexpr int STAGE_B = 4 * TILE_B;   // 40960: Ah, Al, Bh, Bl
static constexpr int SMEM_DYN_GEMM = 2 * STAGE_B;  // 81920

template <bool HAS_BIAS>
__global__ void __launch_bounds__(128, 2) mma_gemm_kernel(
        const __nv_bfloat16* __restrict__ Ah, const __nv_bfloat16* __restrict__ Al,
        const __nv_bfloat16* __restrict__ Bh, const __nv_bfloat16* __restrict__ Bl,
        float* __restrict__ C, const float* __restrict__ bias,
        int K, int Nreal, int ldc) {
    extern __shared__ __align__(128) char smem[];
    const uint32_t sb = smem_u32(smem);
    const int tid  = threadIdx.x;
    const int lane = tid & 31;
    const int wid  = tid >> 5;
    const int row0 = blockIdx.x * 128;
    const int col0 = blockIdx.y * 128;
    const int nc   = K >> 5;                 // BK=32

    // warp tiling: 2 (m) x 2 (n)
    const int m0 = (wid & 1) * 64;
    const int n0 = (wid >> 1) * 64;

    float acc[4][8][4];
    #pragma unroll
    for (int mi = 0; mi < 4; mi++)
        #pragma unroll
        for (int ni = 0; ni < 8; ni++)
            #pragma unroll
            for (int j = 0; j < 4; j++) acc[mi][ni][j] = 0.f;

    // ldmatrix lane address components
    const int q = lane >> 3;
    const uint32_t a_row = (uint32_t)((lane & 7) + (q & 1) * 8);
    const uint32_t a_kb  = (uint32_t)(q >> 1) * 16;
    const uint32_t b_row = (uint32_t)((lane & 7) + (q >> 1) * 8);
    const uint32_t b_kb  = (uint32_t)(q & 1) * 16;

    // ---- stage loader: 16 cp.async of 16B per thread ----
    auto load_stage = [&](uint32_t s, int kt) {
        #pragma unroll
        for (int qq = 0; qq < 4; qq++) {
            int u = tid + 128 * qq;
            int r = u >> 2, cc = u & 3;
            uint32_t so = (uint32_t)(r * RS + cc * 16);
            size_t ga = (size_t)(row0 + r) * K + kt + cc * 8;
            size_t gb = (size_t)(col0 + r) * K + kt + cc * 8;
            CP_ASYNC16(s + so,              Ah + ga);
            CP_ASYNC16(s + TILE_B + so,     Al + ga);
            CP_ASYNC16(s + 2 * TILE_B + so, Bh + gb);
            CP_ASYNC16(s + 3 * TILE_B + so, Bl + gb);
        }
        CP_COMMIT();
    };

    load_stage(sb, 0);

    #pragma unroll 1
    for (int i = 0; i < nc; i++) {
        if (i + 1 < nc) {
            load_stage(sb + ((i + 1) & 1) * STAGE_B, (i + 1) << 5);
            CP_WAIT1();
        } else {
            CP_WAIT0();
        }
        __syncthreads();
        const uint32_t s = sb + (i & 1) * STAGE_B;

        #pragma unroll
        for (int kk = 0; kk < 32; kk += 16) {
            uint32_t ah[4][4], al[4][4];
            #pragma unroll
            for (int mi = 0; mi < 4; mi++) {
                uint32_t aa = s + (uint32_t)(m0 + mi * 16 + a_row) * RS
                            + (uint32_t)kk * 2 + a_kb;
                LDSM_X4(ah[mi], aa);
                LDSM_X4(al[mi], aa + TILE_B);
            }
            uint32_t bh0[8], bh1[8], bl0[8], bl1[8];
            #pragma unroll
            for (int nn = 0; nn < 4; nn++) {
                uint32_t ba = s + 2 * TILE_B
                            + (uint32_t)(n0 + nn * 16 + b_row) * RS
                            + (uint32_t)kk * 2 + b_kb;
                uint32_t t[4];
                LDSM_X4(t, ba);
                bh0[2 * nn] = t[0]; bh1[2 * nn] = t[1];
                bh0[2 * nn + 1] = t[2]; bh1[2 * nn + 1] = t[3];
                LDSM_X4(t, ba + TILE_B);
                bl0[2 * nn] = t[0]; bl1[2 * nn] = t[1];
                bl0[2 * nn + 1] = t[2]; bl1[2 * nn + 1] = t[3];
            }
            #pragma unroll
            for (int mi = 0; mi < 4; mi++)
                #pragma unroll
                for (int ni = 0; ni < 8; ni++)
                    MMA16816(acc[mi][ni], ah[mi], bh0[ni], bh1[ni]);
            #pragma unroll
            for (int mi = 0; mi < 4; mi++)
                #pragma unroll
                for (int ni = 0; ni < 8; ni++)
                    MMA16816(acc[mi][ni], ah[mi], bl0[ni], bl1[ni]);
            #pragma unroll
            for (int mi = 0; mi < 4; mi++)
                #pragma unroll
                for (int ni = 0; ni < 8; ni++)
                    MMA16816(acc[mi][ni], al[mi], bh0[ni], bh1[ni]);
        }
        __syncthreads();
    }

    // ---- epilogue: direct register -> global; bias read raw (unpadded) ----
    const int g  = lane >> 2;
    const int tg = lane & 3;
    #pragma unroll
    for (int mi = 0; mi < 4; mi++) {
        int row = row0 + m0 + mi * 16 + g;
        #pragma unroll
        for (int ni = 0; ni < 8; ni++) {
            int col = col0 + n0 + ni * 8 + tg * 2;
            if (col + 2 <= Nreal) {
                float bx = 0.f, by = 0.f;
                if (HAS_BIAS) { float2 bv = *(const float2*)(bias + col); bx = bv.x; by = bv.y; }
                float2 v0 = make_float2(acc[mi][ni][0] + bx, acc[mi][ni][1] + by);
                float2 v1 = make_float2(acc[mi][ni][2] + bx, acc[mi][ni][3] + by);
                *(float2*)&C[(size_t)row * ldc + col]       = v0;
                *(float2*)&C[(size_t)(row + 8) * ldc + col] = v1;
            }
        }
    }
}

// ===================== fused attention core =================================
// tanh via sigmoid + 4-way batched reciprocal: 1.25 MUFU per tanh.
__global__ void __launch_bounds__(256) attn_kernel(
        const float* __restrict__ w3, const float* __restrict__ bias) {
    __shared__ float fs[40 * 256];
    __shared__ float attns[8][40];
    __shared__ float w3s[256];

    const int tid  = threadIdx.x;
    const int lane = tid & 31;
    const int wid  = tid >> 5;
    const int row0 = blockIdx.x * 8;
    const int b    = row0 >> 9;

    const float* fsrc = d_f + (size_t)b * 40 * 256;
    for (int i = tid; i < 40 * 256 / 4; i += 256)
        ((float4*)fs)[i] = ((const float4*)fsrc)[i];
    w3s[tid] = w3[tid];
    __syncthreads();

    const int row = row0 + wid;
    float e_k[8], ebc_k[8], w32_k[8];
    #pragma unroll
    for (int k = 0; k < 8; k++) {
        int a    = lane + 32 * k;
        e_k[k]   = d_e[(size_t)row * 256 + a];
        ebc_k[k] = (e_k[k] + bias[a]) * TANH_C;
        w32_k[k] = 2.0f * w3s[a];
    }

    // logits
    float l0 = 0.f, l1 = -INFINITY;
    #pragma unroll 1
    for (int t = 0; t < 40; t++) {
        const float* fr = fs + t * 256;
        float w[8];
        #pragma unroll
        for (int k = 0; k < 8; k++) {
            float y = fmaf(fr[lane + 32 * k], TANH_C, ebc_k[k]);
            y = fminf(y, 31.0f);
            w[k] = ex2f(y) + 1.0f;
        }
        float inv[8];
        rcp4(w, inv);
        rcp4(w + 4, inv + 4);
        float acc = 0.f;
        #pragma unroll
        for (int k = 0; k < 8; k++) acc = fmaf(w32_k[k], inv[k], acc);
        #pragma unroll
        for (int off = 16; off; off >>= 1)
            acc += __shfl_xor_sync(FULLMASK, acc, off);
        if (t < 32) { if (lane == t)      l0 = acc; }
        else        { if (lane == t - 32) l1 = acc; }
    }

    // softmax over 40 logits
    float m = fmaxf(l0, l1);
    #pragma unroll
    for (int off = 16; off; off >>= 1)
        m = fmaxf(m, __shfl_xor_sync(FULLMASK, m, off));
    float p0 = __expf(l0 - m);
    float p1 = (lane < 8) ? __expf(l1 - m) : 0.0f;
    float s  = p0 + p1;
    #pragma unroll
    for (int off = 16; off; off >>= 1)
        s += __shfl_xor_sync(FULLMASK, s, off);
    float invs = __fdividef(1.0f, s);
    attns[wid][lane] = p0 * invs;
    if (lane < 8) attns[wid][32 + lane] = p1 * invs;
    __syncwarp();

    // text_attn
    float ta[8] = {0, 0, 0, 0, 0, 0, 0, 0};
    #pragma unroll 1
    for (int t = 0; t < 40; t++) {
        float wgt = attns[wid][t];
        const float* fr = fs + t * 256;
        #pragma unroll
        for (int k = 0; k < 8; k++)
            ta[k] = fmaf(wgt, fr[lane + 32 * k], ta[k]);
    }

    // g = tanh(concat[e, ta, e*ta, e-ta]) -> bf16 hi/lo split
    size_t gbase = (size_t)row * 1024;
    #pragma unroll
    for (int k = 0; k < 8; k++) {
        int a = lane + 32 * k;
        float ev = e_k[k], tv = ta[k];
        float x[4] = {ev, tv, ev * tv, ev - tv};
        float w[4], inv[4];
        #pragma unroll
        for (int j = 0; j < 4; j++) {
            float y = fminf(x[j] * TANH_C, 31.0f);
            w[j] = ex2f(y) + 1.0f;
        }
        rcp4(w, inv);
        #pragma unroll
        for (int j = 0; j < 4; j++) {
            float tval = fmaf(2.0f, inv[j], -1.0f);
            __nv_bfloat16 h, l;
            split_bf16(tval, h, l);
            d_Gh[gbase + j * 256 + a] = h;
            d_Gl[gbase + j * 256 + a] = l;
        }
    }
}

// ===================== launch ===============================================
extern "C" void kernel_launch(void* const* d_in, const int* in_sizes, int n_in,
                              void* d_out, int out_size) {
    const float* video = (const float*)d_in[0];
    const float* text  = (const float*)d_in[1];
    const float* w1    = (const float*)d_in[2];
    const float* w2    = (const float*)d_in[3];
    const float* w3    = (const float*)d_in[4];
    const float* bias  = (const float*)d_in[5];
    const float* w4    = (const float*)d_in[6];
    const float* b4    = (const float*)d_in[7];
    float* out = (float*)d_out;

    float *e_p;
    __nv_bfloat16 *Ah_p, *Al_p, *Gh_p, *Gl_p, *W1Th_p, *W1Tl_p, *W4Th_p, *W4Tl_p;
    cudaGetSymbolAddress((void**)&e_p,    d_e);
    cudaGetSymbolAddress((void**)&Ah_p,   d_Ah);
    cudaGetSymbolAddress((void**)&Al_p,   d_Al);
    cudaGetSymbolAddress((void**)&Gh_p,   d_Gh);
    cudaGetSymbolAddress((void**)&Gl_p,   d_Gl);
    cudaGetSymbolAddress((void**)&W1Th_p, d_W1Th);
    cudaGetSymbolAddress((void**)&W1Tl_p, d_W1Tl);
    cudaGetSymbolAddress((void**)&W4Th_p, d_W4Th);
    cudaGetSymbolAddress((void**)&W4Tl_p, d_W4Tl);

    cudaFuncSetAttribute(mma_gemm_kernel<false>,
                         cudaFuncAttributeMaxDynamicSharedMemorySize, SMEM_DYN_GEMM);
    cudaFuncSetAttribute(mma_gemm_kernel<true>,
                         cudaFuncAttributeMaxDynamicSharedMemorySize, SMEM_DYN_GEMM);

    // prep
    split_kernel<<<(16 * 512 * 1024 / 4 + 255) / 256, 256>>>(video, Ah_p, Al_p,
                                                             16 * 512 * 1024 / 4);
    transpose_split_kernel<<<dim3(256 / 32, 1024 / 32), dim3(32, 8)>>>(
        w1, W1Th_p, W1Tl_p, 1024, 256);
    transpose_split_kernel<<<dim3(512 / 32, 1024 / 32), dim3(32, 8)>>>(
        w4, W4Th_p, W4Tl_p, 1024, 500);
    text_proj_partial_kernel<<<dim3(80, 4), 256>>>(text, w2);
    text_proj_reduce_kernel<<<640, 256>>>();

    // e = video @ w1 : M=8192, N=256, K=1024
    mma_gemm_kernel<false><<<dim3(64, 2), 128, SMEM_DYN_GEMM>>>(
        Ah_p, Al_p, W1Th_p, W1Tl_p, e_p, nullptr, 1024, 256, 256);

    attn_kernel<<<1024, 256>>>(w3, bias);

    // out = g @ w4 + b4 : M=8192, N=512(pad of 500), K=1024
    mma_gemm_kernel<true><<<dim3(64, 4), 128, SMEM_DYN_GEMM>>>(
        Gh_p, Gl_p, W4Th_p, W4Tl_p, out, b4, 1024, 500, 500);
}